// round 5
// baseline (speedup 1.0000x reference)
#include <cuda_runtime.h>
#include <cstdint>
#include <cstddef>

#define HH   32
#define SQ   2048
#define SKK  2048
#define DHH  128
#define BM   128
#define BN   64
#define NTILES (SKK / BN)          // 32
#define NSTAGE 3
#define LSTR 68                    // L smem row stride (floats)
#define VSTR 132                   // V smem row stride (floats)
#define STAGE_L (BM * LSTR)        // 8704 floats
#define STAGE_V (BN * VSTR)        // 8448 floats
#define OFFV_F  (NSTAGE * STAGE_L) // float offset of V region
#define SMEM_FLOATS (NSTAGE * (STAGE_L + STAGE_V))
#define SMEM_BYTES (SMEM_FLOATS * 4)
#define LOG2E 1.4426950408889634f

__device__ __forceinline__ uint32_t f2tf32(float f) {
    uint32_t u;
    asm("cvt.rna.tf32.f32 %0, %1;" : "=r"(u) : "f"(f));
    return u;
}
__device__ __forceinline__ float ex2f(float x) {
    float y;
    asm("ex2.approx.ftz.f32 %0, %1;" : "=f"(y) : "f"(x));
    return y;
}
__device__ __forceinline__ void cp16(uint32_t dst, const float* src) {
    asm volatile("cp.async.cg.shared.global [%0], [%1], 16;\n" :: "r"(dst), "l"(src));
}

__global__ __launch_bounds__(256)
void attn_sink_kernel(const float* __restrict__ logits,
                      const float* __restrict__ value,
                      const float* __restrict__ sinks,
                      float* __restrict__ out)
{
    extern __shared__ float smem[];

    const int qt   = blockIdx.x;      // 0..15
    const int h    = blockIdx.y;      // 0..31
    const int tid  = threadIdx.x;
    const int lane = tid & 31;
    const int wid  = tid >> 5;        // 0..7
    const int mg   = wid >> 1;        // M-group: rows [mg*32, mg*32+32)
    const int ng   = wid & 1;         // N-half:  cols [ng*64, ng*64+64)
    const int lc   = lane & 3;
    const int lr   = lane >> 2;
    const int nb   = ng * 64;

    const float* Lg = logits + ((size_t)h * SQ + (size_t)qt * BM) * SKK;
    const float* Vg = value  + (size_t)h * SKK * DHH;

    const uint32_t sbase = (uint32_t)__cvta_generic_to_shared(smem);

    // ---- staging maps ----
    // L: thread -> row tid>>1 (0..127), col half (tid&1)*32, 8 x 16B contiguous
    const int Lrow = tid >> 1;
    const int Lcol = (tid & 1) * 32;
    const float* Lsrc0 = Lg + (size_t)Lrow * SKK + Lcol;
    const uint32_t Lsm0 = sbase + (uint32_t)(Lrow * LSTR + Lcol) * 4u;
    // V: thread -> row tid>>2 (0..63), col quarter (tid&3)*32, 8 x 16B contiguous
    const int Vrow = tid >> 2;
    const int Vcol = (tid & 3) * 32;
    const float* Vsrc0 = Vg + (size_t)Vrow * DHH + Vcol;
    const uint32_t Vsm0 = sbase + (uint32_t)(OFFV_F + Vrow * VSTR + Vcol) * 4u;

#define STAGE_TILE(stg, kt_)                                                     \
    do {                                                                          \
        const float* ls = Lsrc0 + (size_t)(kt_) * BN;                             \
        uint32_t     ld = Lsm0 + (uint32_t)((stg) * STAGE_L) * 4u;                \
        _Pragma("unroll")                                                         \
        for (int i_ = 0; i_ < 8; ++i_) cp16(ld + i_ * 16u, ls + i_ * 4);          \
        const float* vs = Vsrc0 + (size_t)(kt_) * BN * DHH;                       \
        uint32_t     vd = Vsm0 + (uint32_t)((stg) * STAGE_V) * 4u;                \
        _Pragma("unroll")                                                         \
        for (int i_ = 0; i_ < 8; ++i_) cp16(vd + i_ * 16u, vs + i_ * 4);          \
        asm volatile("cp.async.commit_group;\n");                                 \
    } while (0)

    // prologue: stages 0,1 <- tiles 0,1
    STAGE_TILE(0, 0);
    STAGE_TILE(1, 1);

    // accumulators: [mi][nt][4]
    float acc[2][8][4];
#pragma unroll
    for (int mi = 0; mi < 2; ++mi)
#pragma unroll
        for (int nt = 0; nt < 8; ++nt) {
            acc[mi][nt][0] = 0.f; acc[mi][nt][1] = 0.f;
            acc[mi][nt][2] = 0.f; acc[mi][nt][3] = 0.f;
        }
    float psum[2][2] = {{0.f, 0.f}, {0.f, 0.f}};

    for (int kt = 0; kt < NTILES; ++kt) {
        const int s = kt % NSTAGE;

        if (kt < NTILES - 2) {
            asm volatile("cp.async.wait_group 1;\n");
        } else {
            asm volatile("cp.async.wait_group 0;\n");
        }
        __syncthreads();   // tile kt resident everywhere; stage (kt+2)%3 free

        if (kt + 2 < NTILES) {
            STAGE_TILE((kt + 2) % NSTAGE, kt + 2);
        }

        const float* Ls = smem + s * STAGE_L;
        const float* Vs = smem + OFFV_F + s * STAGE_V;

#pragma unroll
        for (int half = 0; half < 2; ++half) {
            // ---- A fragments from smem (k-col permutation: mma col c <-> mem col 2c) ----
            float2 A[2][4][2];
#pragma unroll
            for (int mi = 0; mi < 2; ++mi) {
                const int r0 = mg * 32 + mi * 16 + lr;
#pragma unroll
                for (int kk = 0; kk < 4; ++kk) {
                    const int col = (half * 4 + kk) * 8 + 2 * lc;
                    A[mi][kk][0] = *(const float2*)(Ls + r0 * LSTR + col);
                    A[mi][kk][1] = *(const float2*)(Ls + (r0 + 8) * LSTR + col);
                }
            }
            // ---- exp -> tf32 probs + partial row sums ----
            uint32_t P[2][4][4];
#pragma unroll
            for (int mi = 0; mi < 2; ++mi)
#pragma unroll
                for (int kk = 0; kk < 4; ++kk) {
                    float p0 = ex2f(A[mi][kk][0].x * LOG2E);
                    float p2 = ex2f(A[mi][kk][0].y * LOG2E);
                    float p1 = ex2f(A[mi][kk][1].x * LOG2E);
                    float p3 = ex2f(A[mi][kk][1].y * LOG2E);
                    psum[mi][0] += p0 + p2;
                    psum[mi][1] += p1 + p3;
                    P[mi][kk][0] = f2tf32(p0);
                    P[mi][kk][1] = f2tf32(p1);
                    P[mi][kk][2] = f2tf32(p2);
                    P[mi][kk][3] = f2tf32(p3);
                }
            // ---- P @ V ----
#pragma unroll
            for (int kk = 0; kk < 4; ++kk) {
                const int k = half * 4 + kk;
                const float* vrow = Vs + (k * 8 + 2 * lc) * VSTR + nb;
#pragma unroll
                for (int nt = 0; nt < 8; ++nt) {
                    uint32_t b0 = __float_as_uint(vrow[nt * 8 + lr]);          // mem row 2c
                    uint32_t b1 = __float_as_uint(vrow[VSTR + nt * 8 + lr]);   // mem row 2c+1
#pragma unroll
                    for (int mi = 0; mi < 2; ++mi) {
                        asm volatile(
                            "mma.sync.aligned.m16n8k8.row.col.f32.tf32.tf32.f32 "
                            "{%0,%1,%2,%3}, {%4,%5,%6,%7}, {%8,%9}, {%0,%1,%2,%3};\n"
                            : "+f"(acc[mi][nt][0]), "+f"(acc[mi][nt][1]),
                              "+f"(acc[mi][nt][2]), "+f"(acc[mi][nt][3])
                            : "r"(P[mi][kk][0]), "r"(P[mi][kk][1]),
                              "r"(P[mi][kk][2]), "r"(P[mi][kk][3]),
                              "r"(b0), "r"(b1));
                    }
                }
            }
        }
        __syncthreads();   // stage s fully consumed before it is refilled
    }

    // ---- reduce row sums over the quad, add sink, normalize ----
#pragma unroll
    for (int mi = 0; mi < 2; ++mi)
#pragma unroll
        for (int j = 0; j < 2; ++j) {
            psum[mi][j] += __shfl_xor_sync(0xffffffffu, psum[mi][j], 1);
            psum[mi][j] += __shfl_xor_sync(0xffffffffu, psum[mi][j], 2);
        }
    const float snk = ex2f(sinks[h] * LOG2E);
    float inv[2][2];
#pragma unroll
    for (int mi = 0; mi < 2; ++mi) {
        inv[mi][0] = 1.0f / (psum[mi][0] + snk);
        inv[mi][1] = 1.0f / (psum[mi][1] + snk);
    }

    float* Ob = out + ((size_t)h * SQ + (size_t)qt * BM) * DHH;
#pragma unroll
    for (int mi = 0; mi < 2; ++mi) {
        const int r0 = mg * 32 + mi * 16 + lr;
        float* O0 = Ob + (size_t)r0 * DHH + nb + 2 * lc;
        float* O1 = Ob + (size_t)(r0 + 8) * DHH + nb + 2 * lc;
#pragma unroll
        for (int nt = 0; nt < 8; ++nt) {
            *(float2*)(O0 + nt * 8) =
                make_float2(acc[mi][nt][0] * inv[mi][0], acc[mi][nt][1] * inv[mi][0]);
            *(float2*)(O1 + nt * 8) =
                make_float2(acc[mi][nt][2] * inv[mi][1], acc[mi][nt][3] * inv[mi][1]);
        }
    }
}

extern "C" void kernel_launch(void* const* d_in, const int* in_sizes, int n_in,
                              void* d_out, int out_size)
{
    const float* logits = (const float*)d_in[0];
    const float* value  = (const float*)d_in[1];
    const float* sinks  = (const float*)d_in[2];
    float* out = (float*)d_out;

    cudaFuncSetAttribute(attn_sink_kernel,
                         cudaFuncAttributeMaxDynamicSharedMemorySize, SMEM_BYTES);

    dim3 grid(SQ / BM, HH, 1);
    attn_sink_kernel<<<grid, 256, SMEM_BYTES>>>(logits, value, sinks, out);
}

// round 6
// speedup vs baseline: 1.1629x; 1.1629x over previous
#include <cuda_runtime.h>
#include <cstdint>
#include <cstddef>

#define HH   32
#define SQ   2048
#define SKK  2048
#define DHH  128
#define BM   128
#define BN   32
#define NTILES (SKK / BN)          // 64
#define LSTR 40                    // L smem row stride (floats) -> conflict-free A LDS.64
#define VSTR 132                   // V smem row stride (floats)
#define LSTAGE (BM * LSTR)         // 5120 floats
#define VSTAGE (BN * VSTR)         // 4224 floats
#define OFFV_F (2 * LSTAGE)        // float offset of V region
#define SMEM_BYTES ((2 * LSTAGE + 2 * VSTAGE) * 4)   // 74752 B
#define LOG2E 1.4426950408889634f

__device__ __forceinline__ float ex2f(float x) {
    float y;
    asm("ex2.approx.ftz.f32 %0, %1;" : "=f"(y) : "f"(x));
    return y;
}
// pack two fp32 -> half2 (lo = first arg): PTX cvt d, a, b puts b in lo
__device__ __forceinline__ uint32_t packh2(float lo, float hi) {
    uint32_t d;
    asm("cvt.rn.f16x2.f32 %0, %1, %2;" : "=r"(d) : "f"(hi), "f"(lo));
    return d;
}
__device__ __forceinline__ void cp16(uint32_t dst, const float* src) {
    asm volatile("cp.async.cg.shared.global [%0], [%1], 16;\n" :: "r"(dst), "l"(src));
}

__global__ __launch_bounds__(128)
void attn_sink_kernel(const float* __restrict__ logits,
                      const float* __restrict__ value,
                      const float* __restrict__ sinks,
                      float* __restrict__ out)
{
    extern __shared__ float smem[];

    const int qt   = blockIdx.x;      // 0..15
    const int h    = blockIdx.y;      // 0..31
    const int tid  = threadIdx.x;
    const int lane = tid & 31;
    const int w    = tid >> 5;        // warp 0..3 owns rows [w*32, w*32+32)
    const int lc   = lane & 3;
    const int lr   = lane >> 2;

    const float* Lg = logits + ((size_t)h * SQ + (size_t)qt * BM) * SKK;
    const float* Vg = value  + (size_t)h * SKK * DHH;

    const uint32_t sbase = (uint32_t)__cvta_generic_to_shared(smem);

    // ---- staging maps ----
    // L: thread -> row tid (0..127), 32 cols = 8 x 16B
    const float*  Lsrc0 = Lg + (size_t)tid * SKK;
    const uint32_t Lsm0 = sbase + (uint32_t)(tid * LSTR) * 4u;
    // V: thread -> row tid>>2 (0..31), col quarter (tid&3)*32 = 8 x 16B
    const int vrow = tid >> 2, vq = tid & 3;
    const float*  Vsrc0 = Vg + (size_t)vrow * DHH + vq * 32;
    const uint32_t Vsm0 = sbase + (uint32_t)(OFFV_F + vrow * VSTR + vq * 32) * 4u;

#define STAGE_TILE(stg, kt_)                                                      \
    do {                                                                          \
        const float* ls = Lsrc0 + (kt_) * BN;                                     \
        uint32_t     ld = Lsm0 + (uint32_t)((stg) * LSTAGE) * 4u;                 \
        _Pragma("unroll")                                                         \
        for (int i_ = 0; i_ < 8; ++i_) cp16(ld + i_ * 16u, ls + i_ * 4);          \
        const float* vs = Vsrc0 + (size_t)(kt_) * BN * DHH;                       \
        uint32_t     vd = Vsm0 + (uint32_t)((stg) * VSTAGE) * 4u;                 \
        _Pragma("unroll")                                                         \
        for (int i_ = 0; i_ < 8; ++i_) cp16(vd + i_ * 16u, vs + i_ * 4);          \
        asm volatile("cp.async.commit_group;\n");                                 \
    } while (0)

    // prologue: tile 0 -> stage 0
    STAGE_TILE(0, 0);

    // accumulators: [mi][nt][4]
    float acc[2][16][4];
#pragma unroll
    for (int mi = 0; mi < 2; ++mi)
#pragma unroll
        for (int nt = 0; nt < 16; ++nt) {
            acc[mi][nt][0] = 0.f; acc[mi][nt][1] = 0.f;
            acc[mi][nt][2] = 0.f; acc[mi][nt][3] = 0.f;
        }
    float psum[2][2] = {{0.f, 0.f}, {0.f, 0.f}};

    for (int kt = 0; kt < NTILES; ++kt) {
        const int s = kt & 1;

        asm volatile("cp.async.wait_group 0;\n");   // tile kt landed
        __syncthreads();                            // visible; other buffer free

        if (kt + 1 < NTILES) STAGE_TILE(s ^ 1, kt + 1);   // overlaps compute below

        const float* Ls = smem + s * LSTAGE;
        const float* Vs = smem + OFFV_F + s * VSTAGE;

        // ---- A fragments: LDS.64 pairs -> exp -> half2 ----
        uint32_t A[2][2][4];   // [mi][kk16][a0..a3]
#pragma unroll
        for (int mi = 0; mi < 2; ++mi) {
            const int r0 = w * 32 + mi * 16 + lr;
#pragma unroll
            for (int kk = 0; kk < 2; ++kk) {
                const int c0 = kk * 16 + 2 * lc;
                float2 x0 = *(const float2*)(Ls + r0 * LSTR + c0);            // (r0,  k0..k0+1)
                float2 x2 = *(const float2*)(Ls + r0 * LSTR + c0 + 8);        // (r0,  k0+8..9)
                float2 x1 = *(const float2*)(Ls + (r0 + 8) * LSTR + c0);      // (r0+8,k0..k0+1)
                float2 x3 = *(const float2*)(Ls + (r0 + 8) * LSTR + c0 + 8);  // (r0+8,k0+8..9)
                float e00 = ex2f(x0.x * LOG2E), e01 = ex2f(x0.y * LOG2E);
                float e20 = ex2f(x2.x * LOG2E), e21 = ex2f(x2.y * LOG2E);
                float e10 = ex2f(x1.x * LOG2E), e11 = ex2f(x1.y * LOG2E);
                float e30 = ex2f(x3.x * LOG2E), e31 = ex2f(x3.y * LOG2E);
                psum[mi][0] += (e00 + e01) + (e20 + e21);
                psum[mi][1] += (e10 + e11) + (e30 + e31);
                A[mi][kk][0] = packh2(e00, e01);   // (row lr,   k 2lc,2lc+1)
                A[mi][kk][1] = packh2(e10, e11);   // (row lr+8, k 2lc,2lc+1)
                A[mi][kk][2] = packh2(e20, e21);   // (row lr,   k 2lc+8,+9)
                A[mi][kk][3] = packh2(e30, e31);   // (row lr+8, k 2lc+8,+9)
            }
        }

        // ---- P @ V : B from fp32 V smem (broadcast LDS.32) + cvt ----
        const float* vcol = Vs + lr;   // col index handled per nt below
#pragma unroll
        for (int nt = 0; nt < 16; ++nt) {
            const float* vc = vcol + nt * 8;
#pragma unroll
            for (int kk = 0; kk < 2; ++kk) {
                const int k0 = kk * 16 + 2 * lc;
                float v00 = vc[(k0    ) * VSTR];
                float v01 = vc[(k0 + 1) * VSTR];
                float v10 = vc[(k0 + 8) * VSTR];
                float v11 = vc[(k0 + 9) * VSTR];
                uint32_t b0 = packh2(v00, v01);
                uint32_t b1 = packh2(v10, v11);
#pragma unroll
                for (int mi = 0; mi < 2; ++mi) {
                    asm volatile(
                        "mma.sync.aligned.m16n8k16.row.col.f32.f16.f16.f32 "
                        "{%0,%1,%2,%3}, {%4,%5,%6,%7}, {%8,%9}, {%0,%1,%2,%3};\n"
                        : "+f"(acc[mi][nt][0]), "+f"(acc[mi][nt][1]),
                          "+f"(acc[mi][nt][2]), "+f"(acc[mi][nt][3])
                        : "r"(A[mi][kk][0]), "r"(A[mi][kk][1]),
                          "r"(A[mi][kk][2]), "r"(A[mi][kk][3]),
                          "r"(b0), "r"(b1));
                }
            }
        }
    }

    // ---- reduce row sums over the quad, add sink, normalize ----
#pragma unroll
    for (int mi = 0; mi < 2; ++mi)
#pragma unroll
        for (int j = 0; j < 2; ++j) {
            psum[mi][j] += __shfl_xor_sync(0xffffffffu, psum[mi][j], 1);
            psum[mi][j] += __shfl_xor_sync(0xffffffffu, psum[mi][j], 2);
        }
    const float snk = ex2f(sinks[h] * LOG2E);
    float inv[2][2];
#pragma unroll
    for (int mi = 0; mi < 2; ++mi) {
        inv[mi][0] = 1.0f / (psum[mi][0] + snk);
        inv[mi][1] = 1.0f / (psum[mi][1] + snk);
    }

    float* Ob = out + ((size_t)h * SQ + (size_t)qt * BM) * DHH;
#pragma unroll
    for (int mi = 0; mi < 2; ++mi) {
        const int r0 = w * 32 + mi * 16 + lr;
        float* O0 = Ob + (size_t)r0 * DHH + 2 * lc;
        float* O1 = Ob + (size_t)(r0 + 8) * DHH + 2 * lc;
#pragma unroll
        for (int nt = 0; nt < 16; ++nt) {
            *(float2*)(O0 + nt * 8) =
                make_float2(acc[mi][nt][0] * inv[mi][0], acc[mi][nt][1] * inv[mi][0]);
            *(float2*)(O1 + nt * 8) =
                make_float2(acc[mi][nt][2] * inv[mi][1], acc[mi][nt][3] * inv[mi][1]);
        }
    }
}

extern "C" void kernel_launch(void* const* d_in, const int* in_sizes, int n_in,
                              void* d_out, int out_size)
{
    const float* logits = (const float*)d_in[0];
    const float* value  = (const float*)d_in[1];
    const float* sinks  = (const float*)d_in[2];
    float* out = (float*)d_out;

    cudaFuncSetAttribute(attn_sink_kernel,
                         cudaFuncAttributeMaxDynamicSharedMemorySize, SMEM_BYTES);

    dim3 grid(SQ / BM, HH, 1);
    attn_sink_kernel<<<grid, 128, SMEM_BYTES>>>(logits, value, sinks, out);
}

// round 7
// speedup vs baseline: 1.4616x; 1.2569x over previous
#include <cuda_runtime.h>
#include <cstdint>
#include <cstddef>

#define HH   32
#define SQ   2048
#define SKK  2048
#define DHH  128
#define BM   128
#define BN   64
#define NTILES (SKK / BN)      // 32
#define VSTRH 136              // half2 units per k2-row (conflict-free LDS)
#define LOG2E 1.4426950408889634f

__device__ __forceinline__ float ex2f(float x) {
    float y;
    asm("ex2.approx.ftz.f32 %0, %1;" : "=f"(y) : "f"(x));
    return y;
}
// pack two fp32 -> half2 with 'lo' in low 16 bits (verified in R6)
__device__ __forceinline__ uint32_t packh2(float lo, float hi) {
    uint32_t d;
    asm("cvt.rn.f16x2.f32 %0, %1, %2;" : "=r"(d) : "f"(hi), "f"(lo));
    return d;
}

__global__ __launch_bounds__(128)
void attn_sink_kernel(const float* __restrict__ logits,
                      const float* __restrict__ value,
                      const float* __restrict__ sinks,
                      float* __restrict__ out)
{
    __shared__ uint32_t Vs[32 * VSTRH];   // 17408 B, single buffer

    const int qt   = blockIdx.x;
    const int h    = blockIdx.y;
    const int tid  = threadIdx.x;
    const int lane = tid & 31;
    const int w    = tid >> 5;            // warp 0..3 owns rows [w*32, w*32+32)
    const int lc   = lane & 3;
    const int lr   = lane >> 2;

    const float* Lg = logits + ((size_t)h * SQ + (size_t)qt * BM) * SKK;
    const float* Vg = value  + (size_t)h * SKK * DHH;

    // A row pointers: [mi*2 + {0:r0, 1:r0+8}]
    const float* Ar[4];
#pragma unroll
    for (int mi = 0; mi < 2; ++mi) {
        const int r0 = w * 32 + mi * 16 + lr;
        Ar[mi * 2]     = Lg + (size_t)r0 * SKK;
        Ar[mi * 2 + 1] = Lg + (size_t)(r0 + 8) * SKK;
    }
    const int cb = 2 * lc;

    // V staging: thread -> k2 = tid>>2 (0..31), n-quarter nb = (tid&3)*32
    const int k2 = tid >> 2, nb = (tid & 3) * 32;
    const float* Vp0 = Vg + (size_t)(2 * k2) * DHH + nb;   // even k row
    const float* Vp1 = Vp0 + DHH;                          // odd  k row
    uint32_t* sts = &Vs[k2 * VSTRH + nb];

    float acc[2][16][4];
#pragma unroll
    for (int mi = 0; mi < 2; ++mi)
#pragma unroll
        for (int nt = 0; nt < 16; ++nt) {
            acc[mi][nt][0] = 0.f; acc[mi][nt][1] = 0.f;
            acc[mi][nt][2] = 0.f; acc[mi][nt][3] = 0.f;
        }
    float psum[2][2] = {{0.f, 0.f}, {0.f, 0.f}};

    // prefetch registers
    float2   raw0[16], raw1[16];   // A raw for halves 0,1 (cols kt*64 + h*32 ...)
    uint32_t vh2[32];              // next V tile, as interleaved half2

#define LDG_A(dst, h_, ktn)                                                        \
    do {                                                                           \
        _Pragma("unroll")                                                          \
        for (int mi_ = 0; mi_ < 2; ++mi_)                                          \
        _Pragma("unroll")                                                          \
        for (int kk_ = 0; kk_ < 2; ++kk_) {                                        \
            const int c_ = (ktn) * BN + ((h_) * 2 + kk_) * 16 + cb;                \
            float2* d_ = &dst[(mi_ * 2 + kk_) * 4];                                \
            d_[0] = *(const float2*)(Ar[mi_ * 2]     + c_);                        \
            d_[1] = *(const float2*)(Ar[mi_ * 2 + 1] + c_);                        \
            d_[2] = *(const float2*)(Ar[mi_ * 2]     + c_ + 8);                    \
            d_[3] = *(const float2*)(Ar[mi_ * 2 + 1] + c_ + 8);                    \
        }                                                                          \
    } while (0)

#define LDG_V(ktn)                                                                 \
    do {                                                                           \
        const float* s0_ = Vp0 + (size_t)(ktn) * BN * DHH;                         \
        const float* s1_ = Vp1 + (size_t)(ktn) * BN * DHH;                         \
        _Pragma("unroll")                                                          \
        for (int c_ = 0; c_ < 8; ++c_) {                                           \
            float4 a_ = *(const float4*)(s0_ + 4 * c_);                            \
            float4 b_ = *(const float4*)(s1_ + 4 * c_);                            \
            vh2[4 * c_ + 0] = packh2(a_.x, b_.x);                                  \
            vh2[4 * c_ + 1] = packh2(a_.y, b_.y);                                  \
            vh2[4 * c_ + 2] = packh2(a_.z, b_.z);                                  \
            vh2[4 * c_ + 3] = packh2(a_.w, b_.w);                                  \
        }                                                                          \
    } while (0)

#define EXP_PACK(raw, P, base_kk)                                                  \
    do {                                                                           \
        _Pragma("unroll")                                                          \
        for (int mi_ = 0; mi_ < 2; ++mi_)                                          \
        _Pragma("unroll")                                                          \
        for (int kk_ = 0; kk_ < 2; ++kk_) {                                        \
            float2* q_ = &raw[(mi_ * 2 + kk_) * 4];                                \
            float e00 = ex2f(q_[0].x * LOG2E), e01 = ex2f(q_[0].y * LOG2E);        \
            float e10 = ex2f(q_[1].x * LOG2E), e11 = ex2f(q_[1].y * LOG2E);        \
            float e20 = ex2f(q_[2].x * LOG2E), e21 = ex2f(q_[2].y * LOG2E);        \
            float e30 = ex2f(q_[3].x * LOG2E), e31 = ex2f(q_[3].y * LOG2E);        \
            psum[mi_][0] += (e00 + e01) + (e20 + e21);                             \
            psum[mi_][1] += (e10 + e11) + (e30 + e31);                             \
            P[mi_][kk_][0] = packh2(e00, e01);                                     \
            P[mi_][kk_][1] = packh2(e10, e11);                                     \
            P[mi_][kk_][2] = packh2(e20, e21);                                     \
            P[mi_][kk_][3] = packh2(e30, e31);                                     \
        }                                                                          \
    } while (0)

#define MMA_HALF(P, kbase)                                                         \
    do {                                                                           \
        _Pragma("unroll")                                                          \
        for (int kk_ = 0; kk_ < 2; ++kk_) {                                        \
            const uint32_t* vr0 = &Vs[(((kbase) + kk_) * 8 + lc) * VSTRH + lr];    \
            const uint32_t* vr1 = vr0 + 4 * VSTRH;                                 \
            _Pragma("unroll")                                                      \
            for (int nt_ = 0; nt_ < 16; ++nt_) {                                   \
                uint32_t b0 = vr0[nt_ * 8];                                        \
                uint32_t b1 = vr1[nt_ * 8];                                        \
                _Pragma("unroll")                                                  \
                for (int mi_ = 0; mi_ < 2; ++mi_) {                                \
                    asm volatile(                                                  \
                        "mma.sync.aligned.m16n8k16.row.col.f32.f16.f16.f32 "       \
                        "{%0,%1,%2,%3}, {%4,%5,%6,%7}, {%8,%9}, {%0,%1,%2,%3};\n"  \
                        : "+f"(acc[mi_][nt_][0]), "+f"(acc[mi_][nt_][1]),          \
                          "+f"(acc[mi_][nt_][2]), "+f"(acc[mi_][nt_][3])           \
                        : "r"(P[mi_][kk_][0]), "r"(P[mi_][kk_][1]),                \
                          "r"(P[mi_][kk_][2]), "r"(P[mi_][kk_][3]),                \
                          "r"(b0), "r"(b1));                                       \
                }                                                                  \
            }                                                                      \
        }                                                                          \
    } while (0)

    // prologue: tile 0 into registers
    LDG_V(0);
    LDG_A(raw0, 0, 0);
    LDG_A(raw1, 1, 0);

    for (int kt = 0; kt < NTILES; ++kt) {
        __syncthreads();   // prior tile's B reads complete
#pragma unroll
        for (int c = 0; c < 8; ++c)
            *(uint4*)(sts + 4 * c) = *(uint4*)&vh2[4 * c];
        __syncthreads();   // V tile visible

        uint32_t P[2][2][4];

        // half 0: exp/pack, prefetch next h0, mma k-blocks 0..1
        EXP_PACK(raw0, P, 0);
        if (kt + 1 < NTILES) LDG_A(raw0, 0, kt + 1);
        MMA_HALF(P, 0);

        // half 1: exp/pack, prefetch next h1 + next V, mma k-blocks 2..3
        EXP_PACK(raw1, P, 2);
        if (kt + 1 < NTILES) {
            LDG_A(raw1, 1, kt + 1);
            LDG_V(kt + 1);
        }
        MMA_HALF(P, 2);
    }

    // ---- reduce row sums over the quad, add sink, normalize ----
#pragma unroll
    for (int mi = 0; mi < 2; ++mi)
#pragma unroll
        for (int j = 0; j < 2; ++j) {
            psum[mi][j] += __shfl_xor_sync(0xffffffffu, psum[mi][j], 1);
            psum[mi][j] += __shfl_xor_sync(0xffffffffu, psum[mi][j], 2);
        }
    const float snk = ex2f(sinks[h] * LOG2E);
    float inv[2][2];
#pragma unroll
    for (int mi = 0; mi < 2; ++mi) {
        inv[mi][0] = 1.0f / (psum[mi][0] + snk);
        inv[mi][1] = 1.0f / (psum[mi][1] + snk);
    }

    float* Ob = out + ((size_t)h * SQ + (size_t)qt * BM) * DHH;
#pragma unroll
    for (int mi = 0; mi < 2; ++mi) {
        const int r0 = w * 32 + mi * 16 + lr;
        float* O0 = Ob + (size_t)r0 * DHH + 2 * lc;
        float* O1 = Ob + (size_t)(r0 + 8) * DHH + 2 * lc;
#pragma unroll
        for (int nt = 0; nt < 16; ++nt) {
            *(float2*)(O0 + nt * 8) =
                make_float2(acc[mi][nt][0] * inv[mi][0], acc[mi][nt][1] * inv[mi][0]);
            *(float2*)(O1 + nt * 8) =
                make_float2(acc[mi][nt][2] * inv[mi][1], acc[mi][nt][3] * inv[mi][1]);
        }
    }
}

extern "C" void kernel_launch(void* const* d_in, const int* in_sizes, int n_in,
                              void* d_out, int out_size)
{
    const float* logits = (const float*)d_in[0];
    const float* value  = (const float*)d_in[1];
    const float* sinks  = (const float*)d_in[2];
    float* out = (float*)d_out;

    dim3 grid(SQ / BM, HH, 1);
    attn_sink_kernel<<<grid, 128>>>(logits, value, sinks, out);
}

// round 8
// speedup vs baseline: 2.2108x; 1.5126x over previous
#include <cuda_runtime.h>
#include <cstdint>
#include <cstddef>

#define HH   32
#define SQ   2048
#define SKK  2048
#define DHH  128
#define BM   128
#define BN   64
#define NTILES (SKK / BN)          // 32
#define VSTR 132                   // floats per V row in smem (128 + 4 pad)
#define LOG2E 1.4426950408889634f

// two V buffers of [BN][VSTR] floats
#define SMEM_BYTES (2 * BN * VSTR * 4)

__device__ __forceinline__ float ex2f(float x) {
    float y;
    asm("ex2.approx.ftz.f32 %0, %1;" : "=f"(y) : "f"(x));
    return y;
}
// pack two fp32 -> half2 with 'lo' in low 16 bits (verified R6/R7)
__device__ __forceinline__ uint32_t packh2(float lo, float hi) {
    uint32_t d;
    asm("cvt.rn.f16x2.f32 %0, %1, %2;" : "=r"(d) : "f"(hi), "f"(lo));
    return d;
}
__device__ __forceinline__ void cp16(uint32_t dst, const float* src) {
    asm volatile("cp.async.cg.shared.global [%0], [%1], 16;\n" :: "r"(dst), "l"(src));
}

__global__ __launch_bounds__(128)
void attn_sink_kernel(const float* __restrict__ logits,
                      const float* __restrict__ value,
                      const float* __restrict__ sinks,
                      float* __restrict__ out)
{
    extern __shared__ float smem[];   // [2][BN][VSTR]

    const int qt   = blockIdx.x;
    const int h    = blockIdx.y;
    const int tid  = threadIdx.x;
    const int lane = tid & 31;
    const int w    = tid >> 5;        // warp 0..3 owns rows [w*32, w*32+32)
    const int lc   = lane & 3;
    const int lr   = lane >> 2;
    const int cb   = 2 * lc;

    const float* Lg = logits + ((size_t)h * SQ + (size_t)qt * BM) * SKK;
    const float* Vg = value  + (size_t)h * SKK * DHH;

    const uint32_t sbase = (uint32_t)__cvta_generic_to_shared(smem);

    // A row pointers: [mi*2 + {0:r0, 1:r0+8}]
    const float* Ar[4];
#pragma unroll
    for (int mi = 0; mi < 2; ++mi) {
        const int r0 = w * 32 + mi * 16 + lr;
        Ar[mi * 2]     = Lg + (size_t)r0 * SKK;
        Ar[mi * 2 + 1] = Lg + (size_t)(r0 + 8) * SKK;
    }

    // ---- V staging (exactly R2): thread -> 16 rows x one float4 column ----
    const int sc  = lane;             // float4 column 0..31
    const int sr0 = w * 16;           // rows [sr0, sr0+16)

    // prologue: stage tile 0 into buffer 0
    {
#pragma unroll
        for (int i = 0; i < 16; ++i) {
            int r = sr0 + i;
            cp16(sbase + (uint32_t)(r * VSTR + sc * 4) * 4u, Vg + (size_t)r * DHH + sc * 4);
        }
        asm volatile("cp.async.commit_group;\n");
    }

    // ---- A half-buffers: raw logits, 16 float2 each ----
    float2 rawA[16], rawB[16];

#define LDG_A(dst, h_, ktn)                                                        \
    do {                                                                           \
        _Pragma("unroll")                                                          \
        for (int mi_ = 0; mi_ < 2; ++mi_)                                          \
        _Pragma("unroll")                                                          \
        for (int kk_ = 0; kk_ < 2; ++kk_) {                                        \
            const int c_ = (ktn) * BN + ((h_) * 2 + kk_) * 16 + cb;                \
            float2* d_ = &dst[(mi_ * 2 + kk_) * 4];                                \
            d_[0] = *(const float2*)(Ar[mi_ * 2]     + c_);                        \
            d_[1] = *(const float2*)(Ar[mi_ * 2 + 1] + c_);                        \
            d_[2] = *(const float2*)(Ar[mi_ * 2]     + c_ + 8);                    \
            d_[3] = *(const float2*)(Ar[mi_ * 2 + 1] + c_ + 8);                    \
        }                                                                          \
    } while (0)

#define EXP_PACK(raw, P)                                                           \
    do {                                                                           \
        _Pragma("unroll")                                                          \
        for (int mi_ = 0; mi_ < 2; ++mi_)                                          \
        _Pragma("unroll")                                                          \
        for (int kk_ = 0; kk_ < 2; ++kk_) {                                        \
            float2* q_ = &raw[(mi_ * 2 + kk_) * 4];                                \
            float e00 = ex2f(q_[0].x * LOG2E), e01 = ex2f(q_[0].y * LOG2E);        \
            float e10 = ex2f(q_[1].x * LOG2E), e11 = ex2f(q_[1].y * LOG2E);        \
            float e20 = ex2f(q_[2].x * LOG2E), e21 = ex2f(q_[2].y * LOG2E);        \
            float e30 = ex2f(q_[3].x * LOG2E), e31 = ex2f(q_[3].y * LOG2E);        \
            psum[mi_][0] += (e00 + e01) + (e20 + e21);                             \
            psum[mi_][1] += (e10 + e11) + (e30 + e31);                             \
            P[mi_][kk_][0] = packh2(e00, e01);                                     \
            P[mi_][kk_][1] = packh2(e10, e11);                                     \
            P[mi_][kk_][2] = packh2(e20, e21);                                     \
            P[mi_][kk_][3] = packh2(e30, e31);                                     \
        }                                                                          \
    } while (0)

    // B from fp32 V smem: 4 broadcast LDS.32 + 2 cvt per (nt,kk)  (verified R6)
#define MMA_HALF(P, kbase)                                                         \
    do {                                                                           \
        _Pragma("unroll")                                                          \
        for (int kk_ = 0; kk_ < 2; ++kk_) {                                        \
            const int k0_ = ((kbase) + kk_) * 16 + cb;                             \
            const float* v0_ = Vs + (size_t)k0_ * VSTR + lr;                       \
            _Pragma("unroll")                                                      \
            for (int nt_ = 0; nt_ < 16; ++nt_) {                                   \
                const float* vc_ = v0_ + nt_ * 8;                                  \
                uint32_t b0 = packh2(vc_[0],        vc_[VSTR]);                    \
                uint32_t b1 = packh2(vc_[8 * VSTR], vc_[9 * VSTR]);                \
                _Pragma("unroll")                                                  \
                for (int mi_ = 0; mi_ < 2; ++mi_) {                                \
                    asm volatile(                                                  \
                        "mma.sync.aligned.m16n8k16.row.col.f32.f16.f16.f32 "       \
                        "{%0,%1,%2,%3}, {%4,%5,%6,%7}, {%8,%9}, {%0,%1,%2,%3};\n"  \
                        : "+f"(acc[mi_][nt_][0]), "+f"(acc[mi_][nt_][1]),          \
                          "+f"(acc[mi_][nt_][2]), "+f"(acc[mi_][nt_][3])           \
                        : "r"(P[mi_][kk_][0]), "r"(P[mi_][kk_][1]),                \
                          "r"(P[mi_][kk_][2]), "r"(P[mi_][kk_][3]),                \
                          "r"(b0), "r"(b1));                                       \
                }                                                                  \
            }                                                                      \
        }                                                                          \
    } while (0)

    float acc[2][16][4];
#pragma unroll
    for (int mi = 0; mi < 2; ++mi)
#pragma unroll
        for (int nt = 0; nt < 16; ++nt) {
            acc[mi][nt][0] = 0.f; acc[mi][nt][1] = 0.f;
            acc[mi][nt][2] = 0.f; acc[mi][nt][3] = 0.f;
        }
    float psum[2][2] = {{0.f, 0.f}, {0.f, 0.f}};

    // prologue A: both halves of tile 0
    LDG_A(rawA, 0, 0);
    LDG_A(rawB, 1, 0);

    for (int kt = 0; kt < NTILES; ++kt) {
        const int cur = kt & 1;

        __syncthreads();   // readers of buf[cur^1] (prev iter) done before refill

        if (kt + 1 < NTILES) {
            const float* Vt = Vg + (size_t)(kt + 1) * BN * DHH;
            uint32_t db = sbase + (uint32_t)((cur ^ 1) * BN * VSTR) * 4u;
#pragma unroll
            for (int i = 0; i < 16; ++i) {
                int r = sr0 + i;
                cp16(db + (uint32_t)(r * VSTR + sc * 4) * 4u, Vt + (size_t)r * DHH + sc * 4);
            }
            asm volatile("cp.async.commit_group;\n");
            asm volatile("cp.async.wait_group 1;\n");   // tile kt's copy complete
        } else {
            asm volatile("cp.async.wait_group 0;\n");
        }
        __syncthreads();   // buf[cur] visible to all warps

        const float* Vs = smem + cur * BN * VSTR;

        uint32_t P[2][2][4];

        // half 0: exp/pack, refill rawA for next tile BEFORE the long mma block
        EXP_PACK(rawA, P);
        if (kt + 1 < NTILES) LDG_A(rawA, 0, kt + 1);
        MMA_HALF(P, 0);

        // half 1
        EXP_PACK(rawB, P);
        if (kt + 1 < NTILES) LDG_A(rawB, 1, kt + 1);
        MMA_HALF(P, 2);
    }

    // ---- reduce row sums over the quad, add sink, normalize ----
#pragma unroll
    for (int mi = 0; mi < 2; ++mi)
#pragma unroll
        for (int j = 0; j < 2; ++j) {
            psum[mi][j] += __shfl_xor_sync(0xffffffffu, psum[mi][j], 1);
            psum[mi][j] += __shfl_xor_sync(0xffffffffu, psum[mi][j], 2);
        }
    const float snk = ex2f(sinks[h] * LOG2E);
    float inv[2][2];
#pragma unroll
    for (int mi = 0; mi < 2; ++mi) {
        inv[mi][0] = 1.0f / (psum[mi][0] + snk);
        inv[mi][1] = 1.0f / (psum[mi][1] + snk);
    }

    float* Ob = out + ((size_t)h * SQ + (size_t)qt * BM) * DHH;
#pragma unroll
    for (int mi = 0; mi < 2; ++mi) {
        const int r0 = w * 32 + mi * 16 + lr;
        float* O0 = Ob + (size_t)r0 * DHH + 2 * lc;
        float* O1 = Ob + (size_t)(r0 + 8) * DHH + 2 * lc;
#pragma unroll
        for (int nt = 0; nt < 16; ++nt) {
            *(float2*)(O0 + nt * 8) =
                make_float2(acc[mi][nt][0] * inv[mi][0], acc[mi][nt][1] * inv[mi][0]);
            *(float2*)(O1 + nt * 8) =
                make_float2(acc[mi][nt][2] * inv[mi][1], acc[mi][nt][3] * inv[mi][1]);
        }
    }
}

extern "C" void kernel_launch(void* const* d_in, const int* in_sizes, int n_in,
                              void* d_out, int out_size)
{
    const float* logits = (const float*)d_in[0];
    const float* value  = (const float*)d_in[1];
    const float* sinks  = (const float*)d_in[2];
    float* out = (float*)d_out;

    cudaFuncSetAttribute(attn_sink_kernel,
                         cudaFuncAttributeMaxDynamicSharedMemorySize, SMEM_BYTES);

    dim3 grid(SQ / BM, HH, 1);
    attn_sink_kernel<<<grid, 128, SMEM_BYTES>>>(logits, value, sinks, out);
}

// round 9
// speedup vs baseline: 2.3597x; 1.0673x over previous
#include <cuda_runtime.h>
#include <cstdint>
#include <cstddef>

#define HH   32
#define SQ   2048
#define SKK  2048
#define DHH  128
#define BM   128
#define BN   64
#define NTILES (SKK / BN)          // 32
#define VSTRH 136                  // half2 (uint32) stride per k2-row in smem
#define LOG2E 1.4426950408889634f

// two half2 V buffers of [32][VSTRH] uint32
#define SMEM_BYTES (2 * 32 * VSTRH * 4)

// V pre-converted to k-interleaved half2: Vh_g[h][k2][n] = (V[2k2][n], V[2k2+1][n])
__device__ uint32_t Vh_g[(size_t)HH * (SKK / 2) * DHH];   // 16 MB scratch

__device__ __forceinline__ float ex2f(float x) {
    float y;
    asm("ex2.approx.ftz.f32 %0, %1;" : "=f"(y) : "f"(x));
    return y;
}
// pack two fp32 -> half2 with 'lo' in low 16 bits (verified R6/R7/R8)
__device__ __forceinline__ uint32_t packh2(float lo, float hi) {
    uint32_t d;
    asm("cvt.rn.f16x2.f32 %0, %1, %2;" : "=r"(d) : "f"(hi), "f"(lo));
    return d;
}
__device__ __forceinline__ void cp16(uint32_t dst, const void* src) {
    asm volatile("cp.async.cg.shared.global [%0], [%1], 16;\n" :: "r"(dst), "l"(src));
}

// ---- kernel 1: V fp32 -> interleaved half2 in GMEM scratch ----
__global__ __launch_bounds__(256)
void convert_v_kernel(const float* __restrict__ value)
{
    const int idx = blockIdx.x * 256 + threadIdx.x;   // over HH*1024*32 float4-groups
    const int n4 = idx & 31;                          // float4 group in row
    const int k2 = (idx >> 5) & 1023;
    const int h  = idx >> 15;
    const float* v0 = value + ((size_t)h * SKK + 2 * (size_t)k2) * DHH + n4 * 4;
    float4 a = *(const float4*)v0;
    float4 b = *(const float4*)(v0 + DHH);
    uint4 o;
    o.x = packh2(a.x, b.x);
    o.y = packh2(a.y, b.y);
    o.z = packh2(a.z, b.z);
    o.w = packh2(a.w, b.w);
    *(uint4*)&Vh_g[((size_t)h * 1024 + k2) * DHH + n4 * 4] = o;
}

// ---- kernel 2: fused sink-softmax @ V ----
__global__ __launch_bounds__(128)
void attn_sink_kernel(const float* __restrict__ logits,
                      const float* __restrict__ sinks,
                      float* __restrict__ out)
{
    extern __shared__ uint32_t smemh[];   // [2][32][VSTRH]

    const int qt   = blockIdx.x;
    const int h    = blockIdx.y;
    const int tid  = threadIdx.x;
    const int lane = tid & 31;
    const int w    = tid >> 5;        // warp 0..3 owns rows [w*32, w*32+32)
    const int lc   = lane & 3;
    const int lr   = lane >> 2;
    const int cb   = 2 * lc;

    const float* Lg = logits + ((size_t)h * SQ + (size_t)qt * BM) * SKK;

    const uint32_t sbase = (uint32_t)__cvta_generic_to_shared(smemh);

    // A row pointers: [mi*2 + {0:r0, 1:r0+8}]
    const float* Ar[4];
#pragma unroll
    for (int mi = 0; mi < 2; ++mi) {
        const int r0 = w * 32 + mi * 16 + lr;
        Ar[mi * 2]     = Lg + (size_t)r0 * SKK;
        Ar[mi * 2 + 1] = Lg + (size_t)(r0 + 8) * SKK;
    }

    // ---- V staging: thread -> k2-row tid>>2 (0..31), n-quarter (tid&3)*32 (8 x 16B) ----
    const int k2l = tid >> 2, nq = tid & 3;
    const uint32_t* Vsrc0 = &Vh_g[((size_t)h * 1024 + k2l) * DHH + nq * 32];
    const uint32_t Vdst0 = sbase + (uint32_t)(k2l * VSTRH + nq * 32) * 4u;

#define STAGE_V(stg, ktn)                                                          \
    do {                                                                           \
        const uint32_t* s_ = Vsrc0 + (size_t)(ktn) * 32 * DHH;                     \
        uint32_t d_ = Vdst0 + (uint32_t)((stg) * 32 * VSTRH) * 4u;                 \
        _Pragma("unroll")                                                          \
        for (int i_ = 0; i_ < 8; ++i_) cp16(d_ + i_ * 16u, s_ + i_ * 4);           \
        asm volatile("cp.async.commit_group;\n");                                  \
    } while (0)

    // prologue: stage tile 0 into buffer 0
    STAGE_V(0, 0);

    // ---- A half-buffers: raw logits, 16 float2 each ----
    float2 rawA[16], rawB[16];

#define LDG_A(dst, h_, ktn)                                                        \
    do {                                                                           \
        _Pragma("unroll")                                                          \
        for (int mi_ = 0; mi_ < 2; ++mi_)                                          \
        _Pragma("unroll")                                                          \
        for (int kk_ = 0; kk_ < 2; ++kk_) {                                        \
            const int c_ = (ktn) * BN + ((h_) * 2 + kk_) * 16 + cb;                \
            float2* d_ = &dst[(mi_ * 2 + kk_) * 4];                                \
            d_[0] = *(const float2*)(Ar[mi_ * 2]     + c_);                        \
            d_[1] = *(const float2*)(Ar[mi_ * 2 + 1] + c_);                        \
            d_[2] = *(const float2*)(Ar[mi_ * 2]     + c_ + 8);                    \
            d_[3] = *(const float2*)(Ar[mi_ * 2 + 1] + c_ + 8);                    \
        }                                                                          \
    } while (0)

#define EXP_PACK(raw, P)                                                           \
    do {                                                                           \
        _Pragma("unroll")                                                          \
        for (int mi_ = 0; mi_ < 2; ++mi_)                                          \
        _Pragma("unroll")                                                          \
        for (int kk_ = 0; kk_ < 2; ++kk_) {                                        \
            float2* q_ = &raw[(mi_ * 2 + kk_) * 4];                                \
            float e00 = ex2f(q_[0].x * LOG2E), e01 = ex2f(q_[0].y * LOG2E);        \
            float e10 = ex2f(q_[1].x * LOG2E), e11 = ex2f(q_[1].y * LOG2E);        \
            float e20 = ex2f(q_[2].x * LOG2E), e21 = ex2f(q_[2].y * LOG2E);        \
            float e30 = ex2f(q_[3].x * LOG2E), e31 = ex2f(q_[3].y * LOG2E);        \
            psum[mi_][0] += (e00 + e01) + (e20 + e21);                             \
            psum[mi_][1] += (e10 + e11) + (e30 + e31);                             \
            P[mi_][kk_][0] = packh2(e00, e01);                                     \
            P[mi_][kk_][1] = packh2(e10, e11);                                     \
            P[mi_][kk_][2] = packh2(e20, e21);                                     \
            P[mi_][kk_][3] = packh2(e30, e31);                                     \
        }                                                                          \
    } while (0)

    // B fragment = one broadcast-free LDS.32 each (R7-verified layout/addressing)
#define MMA_HALF(P, kbase)                                                         \
    do {                                                                           \
        _Pragma("unroll")                                                          \
        for (int kk_ = 0; kk_ < 2; ++kk_) {                                        \
            const uint32_t* vr0 = &Vs[(((kbase) + kk_) * 8 + lc) * VSTRH + lr];    \
            const uint32_t* vr1 = vr0 + 4 * VSTRH;                                 \
            _Pragma("unroll")                                                      \
            for (int nt_ = 0; nt_ < 16; ++nt_) {                                   \
                uint32_t b0 = vr0[nt_ * 8];                                        \
                uint32_t b1 = vr1[nt_ * 8];                                        \
                _Pragma("unroll")                                                  \
                for (int mi_ = 0; mi_ < 2; ++mi_) {                                \
                    asm volatile(                                                  \
                        "mma.sync.aligned.m16n8k16.row.col.f32.f16.f16.f32 "       \
                        "{%0,%1,%2,%3}, {%4,%5,%6,%7}, {%8,%9}, {%0,%1,%2,%3};\n"  \
                        : "+f"(acc[mi_][nt_][0]), "+f"(acc[mi_][nt_][1]),          \
                          "+f"(acc[mi_][nt_][2]), "+f"(acc[mi_][nt_][3])           \
                        : "r"(P[mi_][kk_][0]), "r"(P[mi_][kk_][1]),                \
                          "r"(P[mi_][kk_][2]), "r"(P[mi_][kk_][3]),                \
                          "r"(b0), "r"(b1));                                       \
                }                                                                  \
            }                                                                      \
        }                                                                          \
    } while (0)

    float acc[2][16][4];
#pragma unroll
    for (int mi = 0; mi < 2; ++mi)
#pragma unroll
        for (int nt = 0; nt < 16; ++nt) {
            acc[mi][nt][0] = 0.f; acc[mi][nt][1] = 0.f;
            acc[mi][nt][2] = 0.f; acc[mi][nt][3] = 0.f;
        }
    float psum[2][2] = {{0.f, 0.f}, {0.f, 0.f}};

    // prologue A: both halves of tile 0
    LDG_A(rawA, 0, 0);
    LDG_A(rawB, 1, 0);

    for (int kt = 0; kt < NTILES; ++kt) {
        const int cur = kt & 1;

        __syncthreads();   // readers of buf[cur^1] (prev iter) done before refill

        if (kt + 1 < NTILES) {
            STAGE_V(cur ^ 1, kt + 1);
            asm volatile("cp.async.wait_group 1;\n");   // tile kt's copy complete
        } else {
            asm volatile("cp.async.wait_group 0;\n");
        }
        __syncthreads();   // buf[cur] visible to all warps

        const uint32_t* Vs = smemh + cur * 32 * VSTRH;

        uint32_t P[2][2][4];

        // half 0: exp/pack, refill rawA for next tile BEFORE the long mma block
        EXP_PACK(rawA, P);
        if (kt + 1 < NTILES) LDG_A(rawA, 0, kt + 1);
        MMA_HALF(P, 0);

        // half 1
        EXP_PACK(rawB, P);
        if (kt + 1 < NTILES) LDG_A(rawB, 1, kt + 1);
        MMA_HALF(P, 2);
    }

    // ---- reduce row sums over the quad, add sink, normalize ----
#pragma unroll
    for (int mi = 0; mi < 2; ++mi)
#pragma unroll
        for (int j = 0; j < 2; ++j) {
            psum[mi][j] += __shfl_xor_sync(0xffffffffu, psum[mi][j], 1);
            psum[mi][j] += __shfl_xor_sync(0xffffffffu, psum[mi][j], 2);
        }
    const float snk = ex2f(sinks[h] * LOG2E);
    float inv[2][2];
#pragma unroll
    for (int mi = 0; mi < 2; ++mi) {
        inv[mi][0] = 1.0f / (psum[mi][0] + snk);
        inv[mi][1] = 1.0f / (psum[mi][1] + snk);
    }

    float* Ob = out + ((size_t)h * SQ + (size_t)qt * BM) * DHH;
#pragma unroll
    for (int mi = 0; mi < 2; ++mi) {
        const int r0 = w * 32 + mi * 16 + lr;
        float* O0 = Ob + (size_t)r0 * DHH + 2 * lc;
        float* O1 = Ob + (size_t)(r0 + 8) * DHH + 2 * lc;
#pragma unroll
        for (int nt = 0; nt < 16; ++nt) {
            *(float2*)(O0 + nt * 8) =
                make_float2(acc[mi][nt][0] * inv[mi][0], acc[mi][nt][1] * inv[mi][0]);
            *(float2*)(O1 + nt * 8) =
                make_float2(acc[mi][nt][2] * inv[mi][1], acc[mi][nt][3] * inv[mi][1]);
        }
    }
}

extern "C" void kernel_launch(void* const* d_in, const int* in_sizes, int n_in,
                              void* d_out, int out_size)
{
    const float* logits = (const float*)d_in[0];
    const float* value  = (const float*)d_in[1];
    const float* sinks  = (const float*)d_in[2];
    float* out = (float*)d_out;

    // kernel 1: V fp32 -> interleaved half2 scratch (HH*1024*32 float4-groups)
    convert_v_kernel<<<(HH * 1024 * 32) / 256, 256>>>(value);

    cudaFuncSetAttribute(attn_sink_kernel,
                         cudaFuncAttributeMaxDynamicSharedMemorySize, SMEM_BYTES);

    dim3 grid(SQ / BM, HH, 1);
    attn_sink_kernel<<<grid, 128, SMEM_BYTES>>>(logits, sinks, out);
}

// round 10
// speedup vs baseline: 2.5781x; 1.0926x over previous
#include <cuda_runtime.h>
#include <cstdint>
#include <cstddef>

#define HH   32
#define SQ   2048
#define SKK  2048
#define DHH  128
#define BM   128
#define BN   64
#define NTILES (SKK / BN)          // 32
#define VSTR2 132                  // uint32 stride per k2-row in smem (conflict-free LDS.128)
#define LOG2E 1.4426950408889634f

// two half2 V buffers of [32][VSTR2] uint32
#define SMEM_BYTES (2 * 32 * VSTR2 * 4)

// V scratch: k-interleaved half2, COLUMN-PERMUTED:
//   Vh_g[h][k2][p] with p = (n&7)*16 + (n>>3)  holds half2(V[2k2][n], V[2k2+1][n])
__device__ uint32_t Vh_g[(size_t)HH * (SKK / 2) * DHH];   // 16 MB

__device__ __forceinline__ float ex2f(float x) {
    float y;
    asm("ex2.approx.ftz.f32 %0, %1;" : "=f"(y) : "f"(x));
    return y;
}
// pack two fp32 -> half2 with 'lo' in low 16 bits (verified R6-R9)
__device__ __forceinline__ uint32_t packh2(float lo, float hi) {
    uint32_t d;
    asm("cvt.rn.f16x2.f32 %0, %1, %2;" : "=r"(d) : "f"(hi), "f"(lo));
    return d;
}
__device__ __forceinline__ void cp16(uint32_t dst, const void* src) {
    asm volatile("cp.async.cg.shared.global [%0], [%1], 16;\n" :: "r"(dst), "l"(src));
}

// ---- kernel 1: V fp32 -> permuted interleaved half2 scratch ----
// thread -> (h, k2, tt, lr); reads n = tt*32 + lr + 8j (j=0..3) from rows 2k2, 2k2+1,
// writes uint4 at p = lr*16 + tt*4  (p+j = lr*16 + (tt*4+j) = (n&7)*16 + (n>>3) ✓)
__global__ __launch_bounds__(256)
void convert_v_kernel(const float* __restrict__ value)
{
    const int idx = blockIdx.x * 256 + threadIdx.x;
    const int lr = idx & 7;
    const int tt = (idx >> 3) & 3;
    const int k2 = (idx >> 5) & 1023;
    const int h  = idx >> 15;
    const float* v0 = value + ((size_t)h * SKK + 2 * (size_t)k2) * DHH;
    const float* v1 = v0 + DHH;
    const int n0 = tt * 32 + lr;
    uint4 o;
    o.x = packh2(v0[n0],      v1[n0]);
    o.y = packh2(v0[n0 + 8],  v1[n0 + 8]);
    o.z = packh2(v0[n0 + 16], v1[n0 + 16]);
    o.w = packh2(v0[n0 + 24], v1[n0 + 24]);
    *(uint4*)&Vh_g[((size_t)h * 1024 + k2) * DHH + lr * 16 + tt * 4] = o;
}

// ---- kernel 2: fused sink-softmax @ V ----
__global__ __launch_bounds__(128)
void attn_sink_kernel(const float* __restrict__ logits,
                      const float* __restrict__ sinks,
                      float* __restrict__ out)
{
    extern __shared__ uint32_t smemh[];   // [2][32][VSTR2]

    const int qt   = blockIdx.x;
    const int h    = blockIdx.y;
    const int tid  = threadIdx.x;
    const int lane = tid & 31;
    const int w    = tid >> 5;        // warp 0..3 owns rows [w*32, w*32+32)
    const int lc   = lane & 3;
    const int lr   = lane >> 2;
    const int cb   = 2 * lc;

    const float* Lg = logits + ((size_t)h * SQ + (size_t)qt * BM) * SKK;

    const uint32_t sbase = (uint32_t)__cvta_generic_to_shared(smemh);

    // A row pointers: [mi*2 + {0:r0, 1:r0+8}]
    const float* Ar[4];
#pragma unroll
    for (int mi = 0; mi < 2; ++mi) {
        const int r0 = w * 32 + mi * 16 + lr;
        Ar[mi * 2]     = Lg + (size_t)r0 * SKK;
        Ar[mi * 2 + 1] = Lg + (size_t)(r0 + 8) * SKK;
    }

    // ---- V staging: thread -> k2-row tid>>2 (0..31), quarter (tid&3)*32 (8 x 16B) ----
    const int k2l = tid >> 2, nq = tid & 3;
    const uint32_t* Vsrc0 = &Vh_g[((size_t)h * 1024 + k2l) * DHH + nq * 32];
    const uint32_t Vdst0 = sbase + (uint32_t)(k2l * VSTR2 + nq * 32) * 4u;

#define STAGE_V(stg, ktn)                                                          \
    do {                                                                           \
        const uint32_t* s_ = Vsrc0 + (size_t)(ktn) * 32 * DHH;                     \
        uint32_t d_ = Vdst0 + (uint32_t)((stg) * 32 * VSTR2) * 4u;                 \
        _Pragma("unroll")                                                          \
        for (int i_ = 0; i_ < 8; ++i_) cp16(d_ + i_ * 16u, s_ + i_ * 4);           \
        asm volatile("cp.async.commit_group;\n");                                  \
    } while (0)

    STAGE_V(0, 0);

    float2 rawA[16], rawB[16];

#define LDG_A(dst, h_, ktn)                                                        \
    do {                                                                           \
        _Pragma("unroll")                                                          \
        for (int mi_ = 0; mi_ < 2; ++mi_)                                          \
        _Pragma("unroll")                                                          \
        for (int kk_ = 0; kk_ < 2; ++kk_) {                                        \
            const int c_ = (ktn) * BN + ((h_) * 2 + kk_) * 16 + cb;                \
            float2* d_ = &dst[(mi_ * 2 + kk_) * 4];                                \
            d_[0] = *(const float2*)(Ar[mi_ * 2]     + c_);                        \
            d_[1] = *(const float2*)(Ar[mi_ * 2 + 1] + c_);                        \
            d_[2] = *(const float2*)(Ar[mi_ * 2]     + c_ + 8);                    \
            d_[3] = *(const float2*)(Ar[mi_ * 2 + 1] + c_ + 8);                    \
        }                                                                          \
    } while (0)

#define EXP_PACK(raw, P)                                                           \
    do {                                                                           \
        _Pragma("unroll")                                                          \
        for (int mi_ = 0; mi_ < 2; ++mi_)                                          \
        _Pragma("unroll")                                                          \
        for (int kk_ = 0; kk_ < 2; ++kk_) {                                        \
            float2* q_ = &raw[(mi_ * 2 + kk_) * 4];                                \
            float e00 = ex2f(q_[0].x * LOG2E), e01 = ex2f(q_[0].y * LOG2E);        \
            float e10 = ex2f(q_[1].x * LOG2E), e11 = ex2f(q_[1].y * LOG2E);        \
            float e20 = ex2f(q_[2].x * LOG2E), e21 = ex2f(q_[2].y * LOG2E);        \
            float e30 = ex2f(q_[3].x * LOG2E), e31 = ex2f(q_[3].y * LOG2E);        \
            psum[mi_][0] += (e00 + e01) + (e20 + e21);                             \
            psum[mi_][1] += (e10 + e11) + (e30 + e31);                             \
            P[mi_][kk_][0] = packh2(e00, e01);                                     \
            P[mi_][kk_][1] = packh2(e10, e11);                                     \
            P[mi_][kk_][2] = packh2(e20, e21);                                     \
            P[mi_][kk_][3] = packh2(e30, e31);                                     \
        }                                                                          \
    } while (0)

    // B via LDS.128: 4 consecutive nt per load (permuted layout), conflict-free
#define MMA_HALF(P, kbase)                                                         \
    do {                                                                           \
        _Pragma("unroll")                                                          \
        for (int kk_ = 0; kk_ < 2; ++kk_) {                                        \
            const uint32_t* vr0 = &Vs[(((kbase) + kk_) * 8 + lc) * VSTR2 + lr * 16]; \
            const uint32_t* vr1 = vr0 + 4 * VSTR2;                                 \
            _Pragma("unroll")                                                      \
            for (int g_ = 0; g_ < 4; ++g_) {                                       \
                uint4 B0 = *(const uint4*)(vr0 + g_ * 4);                          \
                uint4 B1 = *(const uint4*)(vr1 + g_ * 4);                          \
                const uint32_t b0a[4] = {B0.x, B0.y, B0.z, B0.w};                  \
                const uint32_t b1a[4] = {B1.x, B1.y, B1.z, B1.w};                  \
                _Pragma("unroll")                                                  \
                for (int e_ = 0; e_ < 4; ++e_) {                                   \
                    const int nt_ = g_ * 4 + e_;                                   \
                    _Pragma("unroll")                                              \
                    for (int mi_ = 0; mi_ < 2; ++mi_) {                            \
                        asm volatile(                                              \
                            "mma.sync.aligned.m16n8k16.row.col.f32.f16.f16.f32 "   \
                            "{%0,%1,%2,%3}, {%4,%5,%6,%7}, {%8,%9}, {%0,%1,%2,%3};\n" \
                            : "+f"(acc[mi_][nt_][0]), "+f"(acc[mi_][nt_][1]),      \
                              "+f"(acc[mi_][nt_][2]), "+f"(acc[mi_][nt_][3])       \
                            : "r"(P[mi_][kk_][0]), "r"(P[mi_][kk_][1]),            \
                              "r"(P[mi_][kk_][2]), "r"(P[mi_][kk_][3]),            \
                              "r"(b0a[e_]), "r"(b1a[e_]));                         \
                    }                                                              \
                }                                                                  \
            }                                                                      \
        }                                                                          \
    } while (0)

    float acc[2][16][4];
#pragma unroll
    for (int mi = 0; mi < 2; ++mi)
#pragma unroll
        for (int nt = 0; nt < 16; ++nt) {
            acc[mi][nt][0] = 0.f; acc[mi][nt][1] = 0.f;
            acc[mi][nt][2] = 0.f; acc[mi][nt][3] = 0.f;
        }
    float psum[2][2] = {{0.f, 0.f}, {0.f, 0.f}};

    LDG_A(rawA, 0, 0);
    LDG_A(rawB, 1, 0);

    for (int kt = 0; kt < NTILES; ++kt) {
        const int cur = kt & 1;

        __syncthreads();   // readers of buf[cur^1] (prev iter) done before refill

        if (kt + 1 < NTILES) {
            STAGE_V(cur ^ 1, kt + 1);
            asm volatile("cp.async.wait_group 1;\n");
        } else {
            asm volatile("cp.async.wait_group 0;\n");
        }
        __syncthreads();   // buf[cur] visible

        const uint32_t* Vs = smemh + cur * 32 * VSTR2;

        uint32_t P[2][2][4];

        EXP_PACK(rawA, P);
        if (kt + 1 < NTILES) LDG_A(rawA, 0, kt + 1);
        MMA_HALF(P, 0);

        EXP_PACK(rawB, P);
        if (kt + 1 < NTILES) LDG_A(rawB, 1, kt + 1);
        MMA_HALF(P, 2);
    }

    // ---- reduce row sums over the quad, add sink, normalize ----
#pragma unroll
    for (int mi = 0; mi < 2; ++mi)
#pragma unroll
        for (int j = 0; j < 2; ++j) {
            psum[mi][j] += __shfl_xor_sync(0xffffffffu, psum[mi][j], 1);
            psum[mi][j] += __shfl_xor_sync(0xffffffffu, psum[mi][j], 2);
        }
    const float snk = ex2f(sinks[h] * LOG2E);
    float inv[2][2];
#pragma unroll
    for (int mi = 0; mi < 2; ++mi) {
        inv[mi][0] = 1.0f / (psum[mi][0] + snk);
        inv[mi][1] = 1.0f / (psum[mi][1] + snk);
    }

    float* Ob = out + ((size_t)h * SQ + (size_t)qt * BM) * DHH;
#pragma unroll
    for (int mi = 0; mi < 2; ++mi) {
        const int r0 = w * 32 + mi * 16 + lr;
        float* O0 = Ob + (size_t)r0 * DHH + 2 * lc;
        float* O1 = Ob + (size_t)(r0 + 8) * DHH + 2 * lc;
#pragma unroll
        for (int nt = 0; nt < 16; ++nt) {
            *(float2*)(O0 + nt * 8) =
                make_float2(acc[mi][nt][0] * inv[mi][0], acc[mi][nt][1] * inv[mi][0]);
            *(float2*)(O1 + nt * 8) =
                make_float2(acc[mi][nt][2] * inv[mi][1], acc[mi][nt][3] * inv[mi][1]);
        }
    }
}

extern "C" void kernel_launch(void* const* d_in, const int* in_sizes, int n_in,
                              void* d_out, int out_size)
{
    const float* logits = (const float*)d_in[0];
    const float* value  = (const float*)d_in[1];
    const float* sinks  = (const float*)d_in[2];
    float* out = (float*)d_out;

    convert_v_kernel<<<(HH * 1024 * 32) / 256, 256>>>(value);

    cudaFuncSetAttribute(attn_sink_kernel,
                         cudaFuncAttributeMaxDynamicSharedMemorySize, SMEM_BYTES);

    dim3 grid(SQ / BM, HH, 1);
    attn_sink_kernel<<<grid, 128, SMEM_BYTES>>>(logits, sinks, out);
}